// round 4
// baseline (speedup 1.0000x reference)
#include <cuda_runtime.h>
#include <math.h>

#define FULL 0xffffffffu
#define NMAT 38400
#define NSWEEP 7
#define WPB 4

// 38400 * 576 = 22118400 floats (88.5 MB) each — allowed __device__ scratch
__device__ float g_s1[22118400];
__device__ float g_s2[22118400];

// ---------------------------------------------------------------------------
// Warp-level parallel Jacobi eigensolver for a symmetric 24x24 matrix.
// Lane j (j<24) holds column j of A in a[24] and column j of V in v[24].
// Round-robin (chess tournament) ordering: 12 disjoint pairs per round,
// 23 rounds per sweep. Rounds are fully unrolled so all register indices
// are compile-time constants (no local-memory spills).
// On exit: v = eigenvector columns, wout = eigenvalue of this lane's column.
// ---------------------------------------------------------------------------
__device__ __forceinline__ void jacobi24(float (&a)[24], float (&v)[24],
                                         float &wout, int lane) {
#pragma unroll
  for (int i = 0; i < 24; i++) v[i] = (i == lane) ? 1.f : 0.f;
  // capture own diagonal element once; maintained incrementally afterwards
  float dp = 0.f;
#pragma unroll
  for (int i = 0; i < 24; i++) dp = (lane == i) ? a[i] : dp;

  for (int sweep = 0; sweep < NSWEEP; sweep++) {
#pragma unroll
    for (int r = 0; r < 23; r++) {
      // partner of this lane in round r (players 0..22 rotate, 23 fixed)
      int partner;
      if (lane >= 24)      partner = lane;
      else if (lane == 23) partner = r;
      else if (lane == r)  partner = 23;
      else                 partner = (2 * r + 23 - lane) % 23;

      // apq = A[partner][lane] : element `partner` of own column (select chain)
      float apq = 0.f;
#pragma unroll
      for (int i = 0; i < 24; i++) apq = (partner == i) ? a[i] : apq;

      float dq = __shfl_sync(FULL, dp, partner);
      bool  isLow = lane <= partner;
      int   low   = isLow ? lane : partner;
      float app   = isLow ? dp : dq;
      float aqq   = isLow ? dq : dp;
      // both lanes of the pair use the low lane's apq (bitwise identical c,s)
      apq = __shfl_sync(FULL, apq, low);

      float c, s, tt;
      if (fabsf(apq) > 1e-30f) {
        float tau = (aqq - app) / (2.0f * apq);
        tt = ((tau >= 0.f) ? 1.f : -1.f) /
             (fabsf(tau) + sqrtf(fmaf(tau, tau, 1.f)));
        c = rsqrtf(fmaf(tt, tt, 1.f));
        s = tt * c;
      } else { c = 1.f; s = 0.f; tt = 0.f; }

      // diagonal update (standard Jacobi): a'pp = app - t*apq, a'qq = aqq + t*apq
      dp = isLow ? fmaf(-tt, apq, app) : fmaf(tt, apq, aqq);

      // column update A <- A*J  (and V <- V*J)
      float se = isLow ? -s : s;
#pragma unroll
      for (int i = 0; i < 24; i++) {
        float b  = __shfl_sync(FULL, a[i], partner);
        a[i] = fmaf(se, b, c * a[i]);
        float bv = __shfl_sync(FULL, v[i], partner);
        v[i] = fmaf(se, bv, c * v[i]);
      }

      // row update A <- J^T * A : 12 disjoint pairs, compile-time indices
#pragma unroll
      for (int k = 0; k < 12; k++) {
        int p = (k == 0) ? r : (r + k) % 23;
        int q = (k == 0) ? 23 : (r + 23 - k) % 23;
        int P = p < q ? p : q;
        int Q = p < q ? q : p;
        float ck = __shfl_sync(FULL, c, P);
        float sk = __shfl_sync(FULL, s, P);
        float xP = a[P], xQ = a[Q];
        a[P] = fmaf(-sk, xQ, ck * xP);
        a[Q] = fmaf( sk, xP, ck * xQ);
      }
    }
  }
  float wl = 0.f;
#pragma unroll
  for (int i = 0; i < 24; i++) wl = (lane == i) ? a[i] : wl;
  wout = wl;
}

// ---------------------------------------------------------------------------
// R = V * diag(f) * V^T.  v = eigenvector columns (lane j holds col j),
// f = f(eigenvalue) of this lane. tb = per-warp smem scratch (>= 600 floats)
// used to transpose V so each lane gets its row of V in registers.
// ---------------------------------------------------------------------------
__device__ __forceinline__ void recompose24(const float (&v)[24], float f,
                                            float (&r)[24], int lane, float *tb) {
  __syncwarp();
  if (lane < 24) {
#pragma unroll
    for (int i = 0; i < 24; i++) tb[lane * 25 + i] = v[i];
  }
  __syncwarp();
  float vt[24];
  int ln = (lane < 24) ? lane : 0;
#pragma unroll
  for (int i = 0; i < 24; i++) vt[i] = tb[i * 25 + ln];

  float m[24];
#pragma unroll
  for (int i = 0; i < 24; i++) { m[i] = v[i] * f; r[i] = 0.f; }
#pragma unroll
  for (int k = 0; k < 24; k++) {
    float coef = vt[k];
#pragma unroll
    for (int i = 0; i < 24; i++)
      r[i] = fmaf(__shfl_sync(FULL, m[i], k), coef, r[i]);
  }
  __syncwarp();
}

// ---------------------------------------------------------------------------
// K1: x -> sym_logm(x) into g_s1. One warp per matrix.
// ---------------------------------------------------------------------------
__global__ void __launch_bounds__(128) k_logm(const float *__restrict__ x) {
  __shared__ float tbuf[WPB][600];
  int wid = threadIdx.x >> 5, lane = threadIdx.x & 31;
  int m = blockIdx.x * WPB + wid;
  const float *src = x + (size_t)m * 576;

  float a[24];
#pragma unroll
  for (int i = 0; i < 24; i++) a[i] = (lane < 24) ? src[i * 24 + lane] : 0.f;

  float v[24], w;
  jacobi24(a, v, w, lane);
  float f = logf(fmaxf(w, 1e-12f));
  float r[24];
  recompose24(v, f, r, lane, tbuf[wid]);

  float *dst = g_s1 + (size_t)m * 576;
  if (lane < 24) {
#pragma unroll
    for (int i = 0; i < 24; i++) dst[i * 24 + lane] = r[i];
  }
}

// ---------------------------------------------------------------------------
// K2: tangent-space aggregation.
// g_s2[g, j] = sum_v A[g, v, j] * g_s1[g, v]   (576-element matrices)
// Block = one group g (25 matrices), 25 warps: warp j computes output j.
// ---------------------------------------------------------------------------
__global__ void __launch_bounds__(800) k_agg(const float *__restrict__ A) {
  __shared__ float As[625];
  int g = blockIdx.x;
  for (int e = threadIdx.x; e < 625; e += 800) As[e] = A[(size_t)g * 625 + e];
  __syncthreads();

  int j = threadIdx.x >> 5;
  int lane = threadIdx.x & 31;
  float av[25];
#pragma unroll
  for (int vv = 0; vv < 25; vv++) av[vv] = As[vv * 25 + j];

  const float *src = g_s1 + (size_t)g * 14400;
  float *dst = g_s2 + ((size_t)g * 25 + j) * 576;
  for (int it = 0; it < 18; it++) {
    int idx = lane + it * 32;
    float acc = 0.f;
#pragma unroll
    for (int vv = 0; vv < 25; vv++)
      acc = fmaf(av[vv], __ldg(src + vv * 576 + idx), acc);
    dst[idx] = acc;
  }
}

// ---------------------------------------------------------------------------
// K3: expm -> W E W^T -> /||.||_F -> powm(0.5) -> out. One warp per matrix.
// ---------------------------------------------------------------------------
__global__ void __launch_bounds__(128) k_final(const float *__restrict__ Wm,
                                               float *__restrict__ out) {
  __shared__ float tbuf[WPB][600];
  int wid = threadIdx.x >> 5, lane = threadIdx.x & 31;
  int m = blockIdx.x * WPB + wid;

  const float *src = g_s2 + (size_t)m * 576;
  float a[24];
#pragma unroll
  for (int i = 0; i < 24; i++) a[i] = (lane < 24) ? src[i * 24 + lane] : 0.f;

  // expm
  float v[24], w;
  jacobi24(a, v, w, lane);
  float f = expf(w);
  float e[24];
  recompose24(v, f, e, lane, tbuf[wid]);

  // congruence z = W * E * W^T
  float wrow[24], wcol[24];
#pragma unroll
  for (int k = 0; k < 24; k++) {
    wrow[k] = (lane < 24) ? Wm[lane * 24 + k] : 0.f;  // W[j][k], j = lane
    wcol[k] = (lane < 24) ? Wm[k * 24 + lane] : 0.f;  // W[k][j] -> col of W
  }
  float t[24];
#pragma unroll
  for (int i = 0; i < 24; i++) t[i] = 0.f;
#pragma unroll
  for (int k = 0; k < 24; k++) {
    float coef = wrow[k];              // T[:,j] = sum_k E[:,k] * W[j][k]
#pragma unroll
    for (int i = 0; i < 24; i++)
      t[i] = fmaf(__shfl_sync(FULL, e[i], k), coef, t[i]);
  }
  float z[24];
#pragma unroll
  for (int i = 0; i < 24; i++) z[i] = 0.f;
#pragma unroll
  for (int k = 0; k < 24; k++) {
    float tk = t[k];                   // Z[:,j] = sum_k W[:,k] * T[k][j]
#pragma unroll
    for (int i = 0; i < 24; i++)
      z[i] = fmaf(__shfl_sync(FULL, wcol[i], k), tk, z[i]);
  }

  // Frobenius normalization
  float ss = 0.f;
  if (lane < 24) {
#pragma unroll
    for (int i = 0; i < 24; i++) ss = fmaf(z[i], z[i], ss);
  }
#pragma unroll
  for (int off = 16; off > 0; off >>= 1) ss += __shfl_xor_sync(FULL, ss, off);
  float inv = rsqrtf(ss);

#pragma unroll
  for (int i = 0; i < 24; i++) a[i] = (lane < 24) ? z[i] * inv : 0.f;

  // powm 0.5
  jacobi24(a, v, w, lane);
  float fs = sqrtf(fmaxf(w, 1e-12f));
  float r[24];
  recompose24(v, fs, r, lane, tbuf[wid]);

  float *dst = out + (size_t)m * 576;
  if (lane < 24) {
#pragma unroll
    for (int i = 0; i < 24; i++) dst[i * 24 + lane] = r[i];
  }
}

// ---------------------------------------------------------------------------
extern "C" void kernel_launch(void *const *d_in, const int *in_sizes, int n_in,
                              void *d_out, int out_size) {
  const float *x = nullptr, *A = nullptr, *Wm = nullptr;
  for (int i = 0; i < n_in; i++) {
    if (in_sizes[i] == 22118400)     x  = (const float *)d_in[i];
    else if (in_sizes[i] == 960000)  A  = (const float *)d_in[i];
    else if (in_sizes[i] == 576)     Wm = (const float *)d_in[i];
  }
  float *out = (float *)d_out;

  k_logm<<<NMAT / WPB, 128>>>(x);
  k_agg<<<1536, 800>>>(A);
  k_final<<<NMAT / WPB, 128>>>(Wm, out);
}

// round 5
// speedup vs baseline: 1.4683x; 1.4683x over previous
#include <cuda_runtime.h>
#include <math.h>

#define FULL 0xffffffffu
#define NMAT 38400
#define NSWEEP 5
#define WPB 4

// 38400 * 576 = 22118400 floats (88.5 MB) each — allowed __device__ scratch
__device__ float g_s1[22118400];
__device__ float g_s2[22118400];

// ---------------------------------------------------------------------------
// Warp-level parallel Jacobi eigensolver for a symmetric 24x24 matrix.
// Lane j (j<24) holds column j of A in a[24] and column j of V in v[24].
// Round-robin ordering: 12 disjoint pairs per round, 23 rounds per sweep.
// Rounds fully unrolled -> all register indices compile-time (no spills).
// On exit: v = eigenvector columns, wout = eigenvalue of this lane's column.
// ---------------------------------------------------------------------------
__device__ __forceinline__ void jacobi24(float (&a)[24], float (&v)[24],
                                         float &wout, int lane) {
#pragma unroll
  for (int i = 0; i < 24; i++) v[i] = (i == lane) ? 1.f : 0.f;
  float dp = 0.f;
#pragma unroll
  for (int i = 0; i < 24; i++) dp = (lane == i) ? a[i] : dp;

  for (int sweep = 0; sweep < NSWEEP; sweep++) {
#pragma unroll
    for (int r = 0; r < 23; r++) {
      int partner;
      if (lane >= 24)      partner = lane;
      else if (lane == 23) partner = r;
      else if (lane == r)  partner = 23;
      else                 partner = (2 * r + 23 - lane) % 23;

      // apq = A[partner][lane] : element `partner` of own column
      float apq = 0.f;
#pragma unroll
      for (int i = 0; i < 24; i++) apq = (partner == i) ? a[i] : apq;

      float dq = __shfl_sync(FULL, dp, partner);
      bool  isLow = lane <= partner;
      int   low   = isLow ? lane : partner;
      float app   = isLow ? dp : dq;
      float aqq   = isLow ? dq : dp;
      apq = __shfl_sync(FULL, apq, low);  // identical c,s on both lanes

      float c, s, tt;
      if (fabsf(apq) > 1e-30f) {
        float tau = (aqq - app) / (2.0f * apq);
        tt = ((tau >= 0.f) ? 1.f : -1.f) /
             (fabsf(tau) + sqrtf(fmaf(tau, tau, 1.f)));
        c = rsqrtf(fmaf(tt, tt, 1.f));
        s = tt * c;
      } else { c = 1.f; s = 0.f; tt = 0.f; }

      dp = isLow ? fmaf(-tt, apq, app) : fmaf(tt, apq, aqq);

      // column update A <- A*J, V <- V*J
      float se = isLow ? -s : s;
#pragma unroll
      for (int i = 0; i < 24; i++) {
        float b  = __shfl_sync(FULL, a[i], partner);
        a[i] = fmaf(se, b, c * a[i]);
        float bv = __shfl_sync(FULL, v[i], partner);
        v[i] = fmaf(se, bv, c * v[i]);
      }

      // row update A <- J^T * A : 12 disjoint pairs, compile-time indices
#pragma unroll
      for (int k = 0; k < 12; k++) {
        int p = (k == 0) ? r : (r + k) % 23;
        int q = (k == 0) ? 23 : (r + 23 - k) % 23;
        int P = p < q ? p : q;
        int Q = p < q ? q : p;
        float ck = __shfl_sync(FULL, c, P);
        float sk = __shfl_sync(FULL, s, P);
        float xP = a[P], xQ = a[Q];
        a[P] = fmaf(-sk, xQ, ck * xP);
        a[Q] = fmaf( sk, xP, ck * xQ);
      }
    }
  }
  float wl = 0.f;
#pragma unroll
  for (int i = 0; i < 24; i++) wl = (lane == i) ? a[i] : wl;
  wout = wl;
}

// ---------------------------------------------------------------------------
// R = U * diag(f) * U^T.  u = columns (lane j holds col j), f = per-lane scalar.
// tb = per-warp smem scratch (>= 600 floats) to transpose U.
// ---------------------------------------------------------------------------
__device__ __forceinline__ void recompose24(const float (&u)[24], float f,
                                            float (&r)[24], int lane, float *tb) {
  __syncwarp();
  if (lane < 24) {
#pragma unroll
    for (int i = 0; i < 24; i++) tb[lane * 25 + i] = u[i];
  }
  __syncwarp();
  float ut[24];
  int ln = (lane < 24) ? lane : 0;
#pragma unroll
  for (int i = 0; i < 24; i++) ut[i] = tb[i * 25 + ln];

  float m[24];
#pragma unroll
  for (int i = 0; i < 24; i++) { m[i] = u[i] * f; r[i] = 0.f; }
#pragma unroll
  for (int k = 0; k < 24; k++) {
    float coef = ut[k];
#pragma unroll
    for (int i = 0; i < 24; i++)
      r[i] = fmaf(__shfl_sync(FULL, m[i], k), coef, r[i]);
  }
  __syncwarp();
}

// ---------------------------------------------------------------------------
// K1: x -> sym_logm(x) into g_s1. One warp per matrix.
// ---------------------------------------------------------------------------
__global__ void __launch_bounds__(128) k_logm(const float *__restrict__ x) {
  __shared__ float tbuf[WPB][600];
  int wid = threadIdx.x >> 5, lane = threadIdx.x & 31;
  int m = blockIdx.x * WPB + wid;
  const float *src = x + (size_t)m * 576;

  float a[24];
#pragma unroll
  for (int i = 0; i < 24; i++) a[i] = (lane < 24) ? src[i * 24 + lane] : 0.f;

  float v[24], w;
  jacobi24(a, v, w, lane);
  float f = logf(fmaxf(w, 1e-12f));
  float r[24];
  recompose24(v, f, r, lane, tbuf[wid]);

  float *dst = g_s1 + (size_t)m * 576;
  if (lane < 24) {
#pragma unroll
    for (int i = 0; i < 24; i++) dst[i * 24 + lane] = r[i];
  }
}

// ---------------------------------------------------------------------------
// K2: tangent-space aggregation.
// g_s2[g, j] = sum_v A[g, v, j] * g_s1[g, v]
// ---------------------------------------------------------------------------
__global__ void __launch_bounds__(800) k_agg(const float *__restrict__ A) {
  __shared__ float As[625];
  int g = blockIdx.x;
  for (int e = threadIdx.x; e < 625; e += 800) As[e] = A[(size_t)g * 625 + e];
  __syncthreads();

  int j = threadIdx.x >> 5;
  int lane = threadIdx.x & 31;
  float av[25];
#pragma unroll
  for (int vv = 0; vv < 25; vv++) av[vv] = As[vv * 25 + j];

  const float *src = g_s1 + (size_t)g * 14400;
  float *dst = g_s2 + ((size_t)g * 25 + j) * 576;
  for (int it = 0; it < 18; it++) {
    int idx = lane + it * 32;
    float acc = 0.f;
#pragma unroll
    for (int vv = 0; vv < 25; vv++)
      acc = fmaf(av[vv], __ldg(src + vv * 576 + idx), acc);
    dst[idx] = acc;
  }
}

// ---------------------------------------------------------------------------
// K3: expm + congruence fused via U = W*V:
//   Z = W expm(L) W^T = (W V) diag(exp w) (W V)^T
// then Frobenius-normalize, powm(0.5). One warp per matrix.
// ---------------------------------------------------------------------------
__global__ void __launch_bounds__(128) k_final(const float *__restrict__ Wm,
                                               float *__restrict__ out) {
  __shared__ float tbuf[WPB][600];
  int wid = threadIdx.x >> 5, lane = threadIdx.x & 31;
  int m = blockIdx.x * WPB + wid;

  const float *src = g_s2 + (size_t)m * 576;
  float a[24];
#pragma unroll
  for (int i = 0; i < 24; i++) a[i] = (lane < 24) ? src[i * 24 + lane] : 0.f;

  // eig of aggregated log-matrix
  float v[24], w;
  jacobi24(a, v, w, lane);
  float f = expf(w);

  // U = W * V  (lane j: u[i] = sum_k W[i][k] * V[k][j]), W cols in registers
  float wcol[24];
#pragma unroll
  for (int i = 0; i < 24; i++)
    wcol[i] = (lane < 24) ? Wm[i * 24 + lane] : 0.f;  // W[i][lane]

  float u[24];
#pragma unroll
  for (int i = 0; i < 24; i++) u[i] = 0.f;
#pragma unroll
  for (int k = 0; k < 24; k++) {
    float vk = v[k];
#pragma unroll
    for (int i = 0; i < 24; i++)
      u[i] = fmaf(__shfl_sync(FULL, wcol[i], k), vk, u[i]);
  }

  // Z = U diag(f) U^T
  float z[24];
  recompose24(u, f, z, lane, tbuf[wid]);

  // Frobenius normalization
  float ss = 0.f;
  if (lane < 24) {
#pragma unroll
    for (int i = 0; i < 24; i++) ss = fmaf(z[i], z[i], ss);
  }
#pragma unroll
  for (int off = 16; off > 0; off >>= 1) ss += __shfl_xor_sync(FULL, ss, off);
  float inv = rsqrtf(ss);

#pragma unroll
  for (int i = 0; i < 24; i++) a[i] = (lane < 24) ? z[i] * inv : 0.f;

  // powm 0.5
  jacobi24(a, v, w, lane);
  float fs = sqrtf(fmaxf(w, 1e-12f));
  float r[24];
  recompose24(v, fs, r, lane, tbuf[wid]);

  float *dst = out + (size_t)m * 576;
  if (lane < 24) {
#pragma unroll
    for (int i = 0; i < 24; i++) dst[i * 24 + lane] = r[i];
  }
}

// ---------------------------------------------------------------------------
extern "C" void kernel_launch(void *const *d_in, const int *in_sizes, int n_in,
                              void *d_out, int out_size) {
  const float *x = nullptr, *A = nullptr, *Wm = nullptr;
  for (int i = 0; i < n_in; i++) {
    if (in_sizes[i] == 22118400)     x  = (const float *)d_in[i];
    else if (in_sizes[i] == 960000)  A  = (const float *)d_in[i];
    else if (in_sizes[i] == 576)     Wm = (const float *)d_in[i];
  }
  float *out = (float *)d_out;

  k_logm<<<NMAT / WPB, 128>>>(x);
  k_agg<<<1536, 800>>>(A);
  k_final<<<NMAT / WPB, 128>>>(Wm, out);
}